// round 8
// baseline (speedup 1.0000x reference)
#include <cuda_runtime.h>

#define NB    8
#define CIN   3
#define NN    32768
#define COUT  128
#define NEDGE 4194304
#define NTOT  262144   // NB * NN

__device__ float  g_T0[NTOT * 4];
__device__ float  g_T1[NTOT * 4];
__device__ float  g_T2[NTOT * 4];
__device__ float  g_T3[NTOT * 4];
__device__ float  g_U[NTOT * 4];      // dis-scaled gather source (reused per hop)
__device__ float  g_Z[NTOT * 4];      // accumulation target (reused per hop)
__device__ float  g_deg[NTOT];
__device__ float  g_dis[NTOT];
__device__ double g_mom[90];          // s[12] then upper-triangular M[78]
__device__ float  g_Wf[12 * COUT];    // BN-folded weights
__device__ float  g_bf[COUT];         // BN-folded bias

__device__ __forceinline__ void red_v4(float* addr, float a, float b, float c) {
    asm volatile("red.global.add.v4.f32 [%0], {%1, %2, %3, %4};"
                 :: "l"(addr), "f"(a), "f"(b), "f"(c), "f"(0.f) : "memory");
}

// ---------------------------------------------------------------------------
// 1) deg[src] += w  (self loops removed) — 4 edges/thread, vectorized streams
// ---------------------------------------------------------------------------
__global__ void __launch_bounds__(256) deg_kernel(const int* __restrict__ ei,
                                                  const float* __restrict__ ew) {
    int base = (blockIdx.x * blockDim.x + threadIdx.x) * 4;
    const int4   s4 = *reinterpret_cast<const int4*>(ei + base);
    const int4   d4 = *reinterpret_cast<const int4*>(ei + NEDGE + base);
    const float4 w4 = *reinterpret_cast<const float4*>(ew + base);
    if (s4.x != d4.x) atomicAdd(&g_deg[s4.x], w4.x);
    if (s4.y != d4.y) atomicAdd(&g_deg[s4.y], w4.y);
    if (s4.z != d4.z) atomicAdd(&g_deg[s4.z], w4.z);
    if (s4.w != d4.w) atomicAdd(&g_deg[s4.w], w4.w);
}

// ---------------------------------------------------------------------------
// 2) prep: T0 from x, dis = rsqrt(deg), U = dis*T0, zero Z and moments
// ---------------------------------------------------------------------------
__global__ void prep_kernel(const float* __restrict__ x) {
    int i = blockIdx.x * blockDim.x + threadIdx.x;
    if (i < NTOT) {
        int b = i >> 15;          // NN = 2^15
        int n = i & (NN - 1);
        const float* xb = x + (size_t)b * CIN * NN + n;
        float4 v;
        v.x = xb[0];
        v.y = xb[NN];
        v.z = xb[2 * NN];
        v.w = 0.f;
        reinterpret_cast<float4*>(g_T0)[i] = v;

        float d = g_deg[i];
        float dis = (d > 0.f) ? rsqrtf(fmaxf(d, 1e-12f)) : 0.f;
        g_dis[i] = dis;
        reinterpret_cast<float4*>(g_U)[i] = make_float4(dis * v.x, dis * v.y, dis * v.z, 0.f);
        reinterpret_cast<float4*>(g_Z)[i] = make_float4(0.f, 0.f, 0.f, 0.f);
    }
    if (blockIdx.x == 0 && threadIdx.x < 90) g_mom[threadIdx.x] = 0.0;
}

// ---------------------------------------------------------------------------
// 3) Edge pass (identical all 3 hops): Z[d] += w * U[s]  — 4 edges/thread
// ---------------------------------------------------------------------------
__global__ void __launch_bounds__(256) edge_kernel(const int* __restrict__ ei,
                                                   const float* __restrict__ ew) {
    int base = (blockIdx.x * blockDim.x + threadIdx.x) * 4;
    const int4   s4 = *reinterpret_cast<const int4*>(ei + base);
    const int4   d4 = *reinterpret_cast<const int4*>(ei + NEDGE + base);
    const float4 w4 = *reinterpret_cast<const float4*>(ew + base);

    float4 u0 = __ldg(reinterpret_cast<const float4*>(g_U) + s4.x);
    float4 u1 = __ldg(reinterpret_cast<const float4*>(g_U) + s4.y);
    float4 u2 = __ldg(reinterpret_cast<const float4*>(g_U) + s4.z);
    float4 u3 = __ldg(reinterpret_cast<const float4*>(g_U) + s4.w);

    if (s4.x != d4.x) red_v4(g_Z + 4 * (size_t)d4.x, w4.x * u0.x, w4.x * u0.y, w4.x * u0.z);
    if (s4.y != d4.y) red_v4(g_Z + 4 * (size_t)d4.y, w4.y * u1.x, w4.y * u1.y, w4.y * u1.z);
    if (s4.z != d4.z) red_v4(g_Z + 4 * (size_t)d4.z, w4.z * u2.x, w4.z * u2.y, w4.z * u2.z);
    if (s4.w != d4.w) red_v4(g_Z + 4 * (size_t)d4.w, w4.w * u3.x, w4.w * u3.y, w4.w * u3.z);
}

// ---------------------------------------------------------------------------
// 4) Node epilogues
//    epi1: T1 = -dis*Z;         U = dis*T1;  Z = 0
//    epi2: T2 = -2*dis*Z - T0;  U = dis*T2;  Z = 0
// ---------------------------------------------------------------------------
__global__ void epi1_kernel() {
    int i = blockIdx.x * blockDim.x + threadIdx.x;
    if (i >= NTOT) return;
    float dis = g_dis[i];
    float4 z = reinterpret_cast<const float4*>(g_Z)[i];
    float4 t = make_float4(-dis * z.x, -dis * z.y, -dis * z.z, 0.f);
    reinterpret_cast<float4*>(g_T1)[i] = t;
    reinterpret_cast<float4*>(g_U)[i]  = make_float4(dis * t.x, dis * t.y, dis * t.z, 0.f);
    reinterpret_cast<float4*>(g_Z)[i]  = make_float4(0.f, 0.f, 0.f, 0.f);
}

__global__ void epi2_kernel() {
    int i = blockIdx.x * blockDim.x + threadIdx.x;
    if (i >= NTOT) return;
    float dis = g_dis[i];
    float4 z  = reinterpret_cast<const float4*>(g_Z)[i];
    float4 t0 = reinterpret_cast<const float4*>(g_T0)[i];
    float m = -2.f * dis;
    float4 t = make_float4(fmaf(m, z.x, -t0.x), fmaf(m, z.y, -t0.y), fmaf(m, z.z, -t0.z), 0.f);
    reinterpret_cast<float4*>(g_T2)[i] = t;
    reinterpret_cast<float4*>(g_U)[i]  = make_float4(dis * t.x, dis * t.y, dis * t.z, 0.f);
    reinterpret_cast<float4*>(g_Z)[i]  = make_float4(0.f, 0.f, 0.f, 0.f);
}

// ---------------------------------------------------------------------------
// 5) epi3 + moments fused: T3 = -2*dis*Z - T1, accumulate s[12], M[78]
// ---------------------------------------------------------------------------
__device__ __forceinline__ float warp_sum(float v) {
    #pragma unroll
    for (int o = 16; o > 0; o >>= 1) v += __shfl_down_sync(0xFFFFFFFFu, v, o);
    return v;
}

__global__ void __launch_bounds__(256) epi3_moments_kernel() {
    float s[12];
    float m[78];
    #pragma unroll
    for (int j = 0; j < 12; j++) s[j] = 0.f;
    #pragma unroll
    for (int j = 0; j < 78; j++) m[j] = 0.f;

    int stride = gridDim.x * blockDim.x;
    for (int i = blockIdx.x * blockDim.x + threadIdx.x; i < NTOT; i += stride) {
        float dis = g_dis[i];
        float4 z  = reinterpret_cast<const float4*>(g_Z)[i];
        float4 t1 = reinterpret_cast<const float4*>(g_T1)[i];
        float mm = -2.f * dis;
        float4 t3 = make_float4(fmaf(mm, z.x, -t1.x), fmaf(mm, z.y, -t1.y),
                                fmaf(mm, z.z, -t1.z), 0.f);
        reinterpret_cast<float4*>(g_T3)[i] = t3;

        float4 t0 = reinterpret_cast<const float4*>(g_T0)[i];
        float4 t2 = reinterpret_cast<const float4*>(g_T2)[i];
        float t[12] = {t0.x, t0.y, t0.z, t1.x, t1.y, t1.z,
                       t2.x, t2.y, t2.z, t3.x, t3.y, t3.z};
        #pragma unroll
        for (int f = 0; f < 12; f++) s[f] += t[f];
        int idx = 0;
        #pragma unroll
        for (int f = 0; f < 12; f++) {
            #pragma unroll
            for (int g = f; g < 12; g++) {
                m[idx] += t[f] * t[g];
                idx++;
            }
        }
    }

    __shared__ float blk[90];
    if (threadIdx.x < 90) blk[threadIdx.x] = 0.f;
    __syncthreads();
    #pragma unroll
    for (int v = 0; v < 12; v++) {
        float val = warp_sum(s[v]);
        if ((threadIdx.x & 31) == 0) atomicAdd(&blk[v], val);
    }
    #pragma unroll
    for (int v = 0; v < 78; v++) {
        float val = warp_sum(m[v]);
        if ((threadIdx.x & 31) == 0) atomicAdd(&blk[12 + v], val);
    }
    __syncthreads();
    if (threadIdx.x < 90) atomicAdd(&g_mom[threadIdx.x], (double)blk[threadIdx.x]);
}

// ---------------------------------------------------------------------------
// 6) Per-channel BN stats from moments; fold BN into weights/bias
// ---------------------------------------------------------------------------
__global__ void stats_kernel(const float* __restrict__ weight, const float* __restrict__ bias,
                             const float* __restrict__ gamma, const float* __restrict__ beta) {
    int c = threadIdx.x;
    if (c >= COUT) return;

    double w[12];
    #pragma unroll
    for (int j = 0; j < 12; j++)
        w[j] = (double)weight[(j / 3) * (CIN * COUT) + (j % 3) * COUT + c];
    double b = (double)bias[c];

    double ws = 0.0;
    #pragma unroll
    for (int j = 0; j < 12; j++) ws += w[j] * g_mom[j];

    double wMw = 0.0;
    int idx = 12;
    #pragma unroll
    for (int f = 0; f < 12; f++) {
        #pragma unroll
        for (int g = f; g < 12; g++) {
            double mv = g_mom[idx++];
            wMw += ((f == g) ? 1.0 : 2.0) * w[f] * w[g] * mv;
        }
    }

    const double T = (double)NTOT;
    double mean  = (ws + T * b) / T;
    double sumsq = wMw + 2.0 * b * ws + T * b * b;
    double var   = sumsq / T - mean * mean;
    double a     = (double)gamma[c] / sqrt(var + 1e-5);

    #pragma unroll
    for (int j = 0; j < 12; j++) g_Wf[j * COUT + c] = (float)(w[j] * a);
    g_bf[c] = (float)((b - mean) * a + (double)beta[c]);
}

// ---------------------------------------------------------------------------
// 7) Final: out[b,c,n] = relu(t_i . w'_c + b'_c)
// ---------------------------------------------------------------------------
__global__ void __launch_bounds__(256) final_kernel(float* __restrict__ out) {
    __shared__ float sW[12][COUT];
    __shared__ float sb[COUT];
    int tid = threadIdx.y * 32 + threadIdx.x;
    for (int idx = tid; idx < 12 * COUT; idx += 256)
        sW[idx / COUT][idx % COUT] = g_Wf[idx];
    if (tid < COUT) sb[tid] = g_bf[tid];
    __syncthreads();

    int i = blockIdx.x * 32 + threadIdx.x;
    int b = i >> 15;
    int n = i & (NN - 1);

    float4 a0 = reinterpret_cast<const float4*>(g_T0)[i];
    float4 a1 = reinterpret_cast<const float4*>(g_T1)[i];
    float4 a2 = reinterpret_cast<const float4*>(g_T2)[i];
    float4 a3 = reinterpret_cast<const float4*>(g_T3)[i];
    float t[12] = {a0.x, a0.y, a0.z, a1.x, a1.y, a1.z,
                   a2.x, a2.y, a2.z, a3.x, a3.y, a3.z};

    float* ob = out + (size_t)b * COUT * NN + n;
    #pragma unroll
    for (int q = 0; q < 16; q++) {
        int c = q * 8 + threadIdx.y;
        float acc = sb[c];
        #pragma unroll
        for (int j = 0; j < 12; j++) acc = fmaf(t[j], sW[j][c], acc);
        ob[(size_t)c * NN] = fmaxf(acc, 0.f);
    }
}

// ---------------------------------------------------------------------------
extern "C" void kernel_launch(void* const* d_in, const int* in_sizes, int n_in,
                              void* d_out, int out_size) {
    const float* x      = (const float*)d_in[0];
    const int*   ei     = (const int*)d_in[1];
    const float* ew     = (const float*)d_in[2];
    const float* weight = (const float*)d_in[3];
    const float* bias   = (const float*)d_in[4];
    const float* gamma  = (const float*)d_in[5];
    const float* beta   = (const float*)d_in[6];
    float* out = (float*)d_out;
    (void)in_sizes; (void)n_in; (void)out_size;

    const int EB4 = NEDGE / 4 / 256;   // 4096  (4 edges/thread)
    const int TB  = NTOT / 256;        // 1024

    void* degPtr = nullptr;
    cudaGetSymbolAddress(&degPtr, g_deg);
    cudaMemsetAsync(degPtr, 0, NTOT * sizeof(float));

    deg_kernel<<<EB4, 256>>>(ei, ew);
    prep_kernel<<<TB, 256>>>(x);       // T0, dis, U = dis*T0, zero Z/mom

    edge_kernel<<<EB4, 256>>>(ei, ew); // Z = A U0
    epi1_kernel<<<TB, 256>>>();        // T1, U1, Z=0
    edge_kernel<<<EB4, 256>>>(ei, ew); // Z = A U1
    epi2_kernel<<<TB, 256>>>();        // T2, U2, Z=0
    edge_kernel<<<EB4, 256>>>(ei, ew); // Z = A U2
    epi3_moments_kernel<<<512, 256>>>();// T3 + moments

    stats_kernel<<<1, 128>>>(weight, bias, gamma, beta);

    dim3 fb(32, 8);
    final_kernel<<<NTOT / 32, fb>>>(out);
}